// round 6
// baseline (speedup 1.0000x reference)
#include <cuda_runtime.h>

#define NT 256

__device__ __forceinline__ int reflect512(int i) {
    i = (i < 0) ? -i : i;
    return (i > 511) ? 1022 - i : i;
}
__device__ __forceinline__ int clamp511(int i) {
    return min(max(i, 0), 511);
}
__device__ __forceinline__ float grayf(const float* __restrict__ base, int off) {
    float r = base[off], g = base[off + 262144], b = base[off + 524288];
    return fmaf(0.1495f, r, fmaf(0.2935f, g, fmaf(0.057f, b, 0.5f)));
}
__device__ __forceinline__ float2 grayf2(const float* __restrict__ base, int off) {
    float2 r = *(const float2*)(base + off);
    float2 g = *(const float2*)(base + off + 262144);
    float2 b = *(const float2*)(base + off + 524288);
    float2 o;
    o.x = fmaf(0.1495f, r.x, fmaf(0.2935f, g.x, fmaf(0.057f, b.x, 0.5f)));
    o.y = fmaf(0.1495f, r.y, fmaf(0.2935f, g.y, fmaf(0.057f, b.y, 0.5f)));
    return o;
}

__global__ __launch_bounds__(NT)
void canny_fused_kernel(const float* __restrict__ in, float* __restrict__ out)
{
    // 64x32 output tile per CTA.  Shared pool with aliasing:
    //   region A (2960 f): sg[40][74]  -> later sb[36][70]   (sg dead after stage 2)
    //   region B (2800 f): th[40][70]  -> later smg[34][70]  (th dead after stage 3)
    //   region C         : scl[34][68] bytes
    __shared__ __align__(16) float poolA[40 * 74];
    __shared__ __align__(16) float poolB[40 * 70];
    __shared__ __align__(16) unsigned char sclbuf[34 * 68];

    float (*sg)[74]  = reinterpret_cast<float(*)[74]>(poolA);
    float (*sb)[70]  = reinterpret_cast<float(*)[70]>(poolA);
    float (*th)[70]  = reinterpret_cast<float(*)[70]>(poolB);
    float (*smg)[70] = reinterpret_cast<float(*)[70]>(poolB);
    unsigned char (*scl)[68] = reinterpret_cast<unsigned char(*)[68]>(sclbuf);

    const int tx = threadIdx.x, ty = threadIdx.y;
    const int bx0 = blockIdx.x * 64, by0 = blockIdx.y * 32;
    const float* base = in + (size_t)blockIdx.z * 786432u;
    const float w0 = 0.054488685f, w1 = 0.24420134f, w2 = 0.40261995f;

    const bool reflX = (blockIdx.x == 0u) | (blockIdx.x == 7u);
    const bool reflY = (blockIdx.y == 0u) | (blockIdx.y == 15u);

    // ---- stage 1: gray 40x72, abs x = bx0-4+lx ----
    if (!(reflX | reflY)) {
        #pragma unroll
        for (int k = 0; k < 5; k++) {
            int ly = ty + 8 * k;
            int off = (by0 - 4 + ly) * 512 + (bx0 - 4);
            *(float2*)&sg[ly][2 * tx] = grayf2(base, off + 2 * tx);
            if (tx < 4) *(float2*)&sg[ly][64 + 2 * tx] = grayf2(base, off + 64 + 2 * tx);
        }
    } else {
        #pragma unroll
        for (int k = 0; k < 5; k++) {
            int ly = ty + 8 * k;
            int ay = by0 - 4 + ly;
            bool yok = (ay >= 0) & (ay < 512);
            #pragma unroll
            for (int h = 0; h < 3; h++) {
                int lx = tx + 32 * h;
                if (h < 2 || tx < 8) {
                    int ax = bx0 - 4 + lx;
                    float g = 0.0f;
                    if (yok && ax >= 0 && ax < 512) g = grayf(base, ay * 512 + ax);
                    sg[ly][lx] = g;
                }
            }
        }
    }
    __syncthreads();

    // ---- stage 2: horizontal blur -> th cols 0..67, abs x = clamp(bx0-2+j) ----
    if (!reflX) {
        #pragma unroll
        for (int k = 0; k < 5; k++) {
            int ly = ty + 8 * k;
            #pragma unroll
            for (int h = 0; h < 2; h++) {
                int p = tx + 32 * h;
                if (h == 0 || tx < 2) {
                    float2 v0 = *(const float2*)&sg[ly][2 * p];
                    float2 v1 = *(const float2*)&sg[ly][2 * p + 2];
                    float2 v2 = *(const float2*)&sg[ly][2 * p + 4];
                    float2 o;
                    o.x = w0 * (v0.x + v2.x) + w1 * (v0.y + v1.y) + w2 * v1.x;
                    o.y = w0 * (v0.y + v2.y) + w1 * (v1.x + v2.x) + w2 * v1.y;
                    *(float2*)&th[ly][2 * p] = o;
                }
            }
        }
    } else {
        const int ox = bx0 - 4;
        #pragma unroll
        for (int k = 0; k < 5; k++) {
            int ly = ty + 8 * k;
            #pragma unroll
            for (int h = 0; h < 3; h++) {
                int j = tx + 32 * h;
                if (h < 2 || tx < 4) {
                    int cx = clamp511(bx0 - 2 + j);
                    th[ly][j] = w0 * (sg[ly][reflect512(cx - 2) - ox] + sg[ly][reflect512(cx + 2) - ox])
                              + w1 * (sg[ly][reflect512(cx - 1) - ox] + sg[ly][reflect512(cx + 1) - ox])
                              + w2 * sg[ly][reflect512(cx) - ox];
                }
            }
        }
    }
    __syncthreads();

    // ---- stage 3: vertical blur -> sb rows 0..35 (aliases sg; sg dead), abs y = clamp(by0-2+i) ----
    #pragma unroll
    for (int k = 0; k < 5; k++) {
        int i = ty + 8 * k;
        if (i < 36) {
            int r0, r1, r2, r3, r4;
            if (!reflY) { r0 = i; r1 = i + 1; r2 = i + 2; r3 = i + 3; r4 = i + 4; }
            else {
                int cy = clamp511(by0 - 2 + i), oy = by0 - 4;
                r0 = reflect512(cy - 2) - oy; r1 = reflect512(cy - 1) - oy;
                r2 = reflect512(cy) - oy;
                r3 = reflect512(cy + 1) - oy; r4 = reflect512(cy + 2) - oy;
            }
            #pragma unroll
            for (int h = 0; h < 2; h++) {
                int p = tx + 32 * h;
                if (h == 0 || tx < 2) {
                    float2 a = *(const float2*)&th[r0][2 * p];
                    float2 b = *(const float2*)&th[r1][2 * p];
                    float2 c = *(const float2*)&th[r2][2 * p];
                    float2 d = *(const float2*)&th[r3][2 * p];
                    float2 e = *(const float2*)&th[r4][2 * p];
                    float2 o;
                    o.x = w0 * (a.x + e.x) + w1 * (b.x + d.x) + w2 * c.x;
                    o.y = w0 * (a.y + e.y) + w1 * (b.y + d.y) + w2 * c.y;
                    *(float2*)&sb[i][2 * p] = o;
                }
            }
        }
    }
    __syncthreads();

    // ---- stage 4: Sobel + magnitude + class; smg aliases th (th dead). j valid 1..66 ----
    #pragma unroll
    for (int k = 0; k < 5; k++) {
        int i = ty + 8 * k;
        if (i < 34) {
            #pragma unroll
            for (int h = 0; h < 2; h++) {
                int p = tx + 32 * h;
                if (h == 0 || tx < 2) {
                    int qm = max(p - 1, 0), qp = min(p + 1, 33);
                    float2 a0 = *(const float2*)&sb[i    ][2 * qm];
                    float2 b0 = *(const float2*)&sb[i    ][2 * p ];
                    float2 c0 = *(const float2*)&sb[i    ][2 * qp];
                    float2 a1 = *(const float2*)&sb[i + 1][2 * qm];
                    float2 b1 = *(const float2*)&sb[i + 1][2 * p ];
                    float2 c1 = *(const float2*)&sb[i + 1][2 * qp];
                    float2 a2 = *(const float2*)&sb[i + 2][2 * qm];
                    float2 b2 = *(const float2*)&sb[i + 2][2 * p ];
                    float2 c2 = *(const float2*)&sb[i + 2][2 * qp];

                    float gx0 = (b0.y - a0.y) + 2.0f * (b1.y - a1.y) + (b2.y - a2.y);
                    float gy0 = (a2.y - a0.y) + 2.0f * (b2.x - b0.x) + (b2.y - b0.y);
                    float gx1 = (c0.x - b0.x) + 2.0f * (c1.x - b1.x) + (c2.x - b2.x);
                    float gy1 = (b2.x - b0.x) + 2.0f * (b2.y - b0.y) + (c2.x - c0.x);

                    float2 m;
                    m.x = sqrtf(fmaf(gx0, gx0, fmaf(gy0, gy0, 1e-6f)));
                    m.y = sqrtf(fmaf(gx1, gx1, fmaf(gy1, gy1, 1e-6f)));
                    *(float2*)&smg[i][2 * p] = m;

                    const float T = 0.41421356237309503f;  // tan(22.5 deg)
                    float ax0 = fabsf(gx0), ay0 = fabsf(gy0);
                    int c0i;
                    if (ay0 <= T * ax0)      c0i = 0;
                    else if (ax0 <= T * ay0) c0i = 2;
                    else c0i = ((__float_as_int(gx0) ^ __float_as_int(gy0)) >= 0) ? 1 : 3;
                    float ax1 = fabsf(gx1), ay1 = fabsf(gy1);
                    int c1i;
                    if (ay1 <= T * ax1)      c1i = 0;
                    else if (ax1 <= T * ay1) c1i = 2;
                    else c1i = ((__float_as_int(gx1) ^ __float_as_int(gy1)) >= 0) ? 1 : 3;
                    uchar2 cc; cc.x = (unsigned char)c0i; cc.y = (unsigned char)c1i;
                    *(uchar2*)&scl[i][2 * p] = cc;
                }
            }
        }
    }
    __syncthreads();

    // ---- stage 5: NMS + store (2 px/thread/iter) ----
    const unsigned DY = 0x0001u, DX = 0x0122u;
    const bool border = reflX | reflY;

    #pragma unroll
    for (int k = 0; k < 4; k++) {
        int iy = ty + 8 * k;
        int ii = iy + 1;
        int jj = 2 * tx + 2;
        float2 mc = *(const float2*)&smg[ii][jj];
        uchar2 cc = *(const uchar2*)&scl[ii][jj];

        int s0 = cc.x * 4;
        int dy0 = (int)((DY >> s0) & 0xFu) - 1;
        int dx0 = (int)((DX >> s0) & 0xFu) - 1;
        float mp0 = smg[ii + dy0][jj + dx0];
        float mq0 = smg[ii - dy0][jj - dx0];

        int s1 = cc.y * 4;
        int dy1 = (int)((DY >> s1) & 0xFu) - 1;
        int dx1 = (int)((DX >> s1) & 0xFu) - 1;
        float mp1 = smg[ii + dy1][jj + 1 + dx1];
        float mq1 = smg[ii - dy1][jj + 1 - dx1];

        if (border) {
            int ay = by0 + iy;
            int ax = bx0 + 2 * tx;
            if (!((unsigned)(ay + dy0) < 512u && (unsigned)(ax + dx0) < 512u)) mp0 = 0.0f;
            if (!((unsigned)(ay - dy0) < 512u && (unsigned)(ax - dx0) < 512u)) mq0 = 0.0f;
            if (!((unsigned)(ay + dy1) < 512u && (unsigned)(ax + 1 + dx1) < 512u)) mp1 = 0.0f;
            if (!((unsigned)(ay - dy1) < 512u && (unsigned)(ax + 1 - dx1) < 512u)) mq1 = 0.0f;
        }

        float2 r;
        r.x = (mc.x > mp0 && mc.x > mq0) ? mc.x : 0.0f;
        r.y = (mc.y > mp1 && mc.y > mq1) ? mc.y : 0.0f;
        *(float2*)&out[((size_t)blockIdx.z * 512 + (by0 + iy)) * 512 + bx0 + 2 * tx] = r;
    }
}

extern "C" void kernel_launch(void* const* d_in, const int* in_sizes, int n_in,
                              void* d_out, int out_size)
{
    (void)in_sizes; (void)n_in; (void)out_size;
    const float* data = (const float*)d_in[0];
    float* out = (float*)d_out;

    dim3 grid(8, 16, 16);
    dim3 block(32, 8);
    canny_fused_kernel<<<grid, block>>>(data, out);
}

// round 7
// speedup vs baseline: 1.5021x; 1.5021x over previous
#include <cuda_runtime.h>

#define NT 256

__device__ __forceinline__ int reflect512(int i) {
    i = (i < 0) ? -i : i;
    return (i > 511) ? 1022 - i : i;
}
__device__ __forceinline__ int clamp511(int i) {
    return min(max(i, 0), 511);
}
__device__ __forceinline__ float grayf(const float* __restrict__ base, int off) {
    float r = base[off], g = base[off + 262144], b = base[off + 524288];
    return fmaf(0.1495f, r, fmaf(0.2935f, g, fmaf(0.057f, b, 0.5f)));
}
__device__ __forceinline__ int octclass(float gx, float gy) {
    const float T = 0.41421356237309503f;  // tan(22.5 deg)
    float ax = fabsf(gx), ay = fabsf(gy);
    if (ay <= T * ax) return 0;
    if (ax <= T * ay) return 2;
    return ((__float_as_int(gx) ^ __float_as_int(gy)) >= 0) ? 1 : 3;
}
__device__ __forceinline__ float magf(float gx, float gy) {
    return sqrtf(fmaf(gx, gx, fmaf(gy, gy, 1e-6f)));
}

__global__ __launch_bounds__(NT)
void canny_fused_kernel(const float* __restrict__ in, float* __restrict__ out)
{
    // 64x32 output tile. All row strides = 76 floats (rows 16B aligned).
    //   poolA: sg[40][76] (gray, cols 0..71 valid) -> sb[36][76] (blur, cols 0..67 valid)
    //   poolB: th[40][76] (hblur, cols 0..67 valid) -> smg[34][76] (mag, cols 1..66 valid)
    __shared__ __align__(16) float poolA[40 * 76];
    __shared__ __align__(16) float poolB[40 * 76];
    __shared__ __align__(16) unsigned char sclbuf[34 * 76];

    float (*sg)[76]  = reinterpret_cast<float(*)[76]>(poolA);
    float (*sb)[76]  = reinterpret_cast<float(*)[76]>(poolA);
    float (*th)[76]  = reinterpret_cast<float(*)[76]>(poolB);
    float (*smg)[76] = reinterpret_cast<float(*)[76]>(poolB);
    unsigned char (*scl)[76] = reinterpret_cast<unsigned char(*)[76]>(sclbuf);

    const int tid = threadIdx.x;
    const int bx0 = blockIdx.x * 64, by0 = blockIdx.y * 32;
    const float* base = in + (size_t)blockIdx.z * 786432u;
    const float w0 = 0.054488685f, w1 = 0.24420134f, w2 = 0.40261995f;

    const bool reflX = (blockIdx.x == 0u) | (blockIdx.x == 7u);
    const bool reflY = (blockIdx.y == 0u) | (blockIdx.y == 15u);

    // ---- stage 1: gray 40 rows x 72 cols (18 float4 groups), abs x = bx0-4+lx ----
    if (!(reflX | reflY)) {
        #pragma unroll
        for (int k = 0; k < 3; k++) {
            int u = tid + k * NT;
            if (u < 720) {
                int ly = u / 18, g = u - ly * 18;
                int off = (by0 - 4 + ly) * 512 + (bx0 - 4) + 4 * g;
                float4 r  = *(const float4*)(base + off);
                float4 gg = *(const float4*)(base + off + 262144);
                float4 bb = *(const float4*)(base + off + 524288);
                float4 o;
                o.x = fmaf(0.1495f, r.x, fmaf(0.2935f, gg.x, fmaf(0.057f, bb.x, 0.5f)));
                o.y = fmaf(0.1495f, r.y, fmaf(0.2935f, gg.y, fmaf(0.057f, bb.y, 0.5f)));
                o.z = fmaf(0.1495f, r.z, fmaf(0.2935f, gg.z, fmaf(0.057f, bb.z, 0.5f)));
                o.w = fmaf(0.1495f, r.w, fmaf(0.2935f, gg.w, fmaf(0.057f, bb.w, 0.5f)));
                *(float4*)&sg[ly][4 * g] = o;
            }
        }
    } else {
        for (int u = tid; u < 40 * 72; u += NT) {
            int ly = u / 72, lx = u - ly * 72;
            int ay = by0 - 4 + ly, ax = bx0 - 4 + lx;
            float g = 0.0f;
            if ((unsigned)ay < 512u && (unsigned)ax < 512u) g = grayf(base, ay * 512 + ax);
            sg[ly][lx] = g;
        }
    }
    __syncthreads();

    // ---- stage 2: horizontal blur, out col j <- sg[j..j+4]; 40 x 18 groups ----
    if (!reflX) {
        #pragma unroll
        for (int k = 0; k < 3; k++) {
            int u = tid + k * NT;
            if (u < 720) {
                int ly = u / 18, g = u - ly * 18;
                float4 v0 = *(const float4*)&sg[ly][4 * g];
                float4 v1 = *(const float4*)&sg[ly][4 * g + 4];
                float4 o;
                o.x = w0 * (v0.x + v1.x) + w1 * (v0.y + v0.w) + w2 * v0.z;
                o.y = w0 * (v0.y + v1.y) + w1 * (v0.z + v1.x) + w2 * v0.w;
                o.z = w0 * (v0.z + v1.z) + w1 * (v0.w + v1.y) + w2 * v1.x;
                o.w = w0 * (v0.w + v1.w) + w1 * (v1.x + v1.z) + w2 * v1.y;
                *(float4*)&th[ly][4 * g] = o;
            }
        }
    } else {
        const int ox = bx0 - 4;
        for (int u = tid; u < 40 * 68; u += NT) {
            int ly = u / 68, j = u - ly * 68;
            int cx = clamp511(bx0 - 2 + j);
            th[ly][j] = w0 * (sg[ly][reflect512(cx - 2) - ox] + sg[ly][reflect512(cx + 2) - ox])
                      + w1 * (sg[ly][reflect512(cx - 1) - ox] + sg[ly][reflect512(cx + 1) - ox])
                      + w2 * sg[ly][reflect512(cx) - ox];
        }
    }
    __syncthreads();

    // ---- stage 3: vertical blur -> sb rows 0..35 (aliases sg); 36 x 18 groups ----
    #pragma unroll
    for (int k = 0; k < 3; k++) {
        int u = tid + k * NT;
        if (u < 648) {
            int i = u / 18, g = u - i * 18;
            int r0, r1, r2, r3, r4;
            if (!reflY) { r0 = i; r1 = i + 1; r2 = i + 2; r3 = i + 3; r4 = i + 4; }
            else {
                int cy = clamp511(by0 - 2 + i), oy = by0 - 4;
                r0 = reflect512(cy - 2) - oy; r1 = reflect512(cy - 1) - oy;
                r2 = reflect512(cy) - oy;
                r3 = reflect512(cy + 1) - oy; r4 = reflect512(cy + 2) - oy;
            }
            float4 a = *(const float4*)&th[r0][4 * g];
            float4 b = *(const float4*)&th[r1][4 * g];
            float4 c = *(const float4*)&th[r2][4 * g];
            float4 d = *(const float4*)&th[r3][4 * g];
            float4 e = *(const float4*)&th[r4][4 * g];
            float4 o;
            o.x = w0 * (a.x + e.x) + w1 * (b.x + d.x) + w2 * c.x;
            o.y = w0 * (a.y + e.y) + w1 * (b.y + d.y) + w2 * c.y;
            o.z = w0 * (a.z + e.z) + w1 * (b.z + d.z) + w2 * c.z;
            o.w = w0 * (a.w + e.w) + w1 * (b.w + d.w) + w2 * c.w;
            *(float4*)&sb[i][4 * g] = o;
        }
    }
    __syncthreads();

    // ---- stage 4: Sobel + magnitude + class -> smg (aliases th), scl; 34 x 18 groups ----
    #pragma unroll
    for (int k = 0; k < 3; k++) {
        int u = tid + k * NT;
        if (u < 612) {
            int i = u / 18, g = u - i * 18;
            int cm = max(4 * g - 1, 0);
            float  m0 = sb[i    ][cm];
            float4 v0 = *(const float4*)&sb[i    ][4 * g];
            float  p0 = sb[i    ][4 * g + 4];
            float  m1 = sb[i + 1][cm];
            float4 v1 = *(const float4*)&sb[i + 1][4 * g];
            float  p1 = sb[i + 1][4 * g + 4];
            float  m2 = sb[i + 2][cm];
            float4 v2 = *(const float4*)&sb[i + 2][4 * g];
            float  p2 = sb[i + 2][4 * g + 4];

            // px t: cols (left, center, right) over rows 0..2
            float4 mg; uchar4 cc;
            {   // t=0: l=(m0,m1,m2) c=(v0.x,v1.x,v2.x) r=(v0.y,v1.y,v2.y)
                float gx = (v0.y - m0) + 2.0f * (v1.y - m1) + (v2.y - m2);
                float gy = (m2 - m0) + 2.0f * (v2.x - v0.x) + (v2.y - v0.y);
                mg.x = magf(gx, gy); cc.x = (unsigned char)octclass(gx, gy);
            }
            {   // t=1
                float gx = (v0.z - v0.x) + 2.0f * (v1.z - v1.x) + (v2.z - v2.x);
                float gy = (v2.x - v0.x) + 2.0f * (v2.y - v0.y) + (v2.z - v0.z);
                mg.y = magf(gx, gy); cc.y = (unsigned char)octclass(gx, gy);
            }
            {   // t=2
                float gx = (v0.w - v0.y) + 2.0f * (v1.w - v1.y) + (v2.w - v2.y);
                float gy = (v2.y - v0.y) + 2.0f * (v2.z - v0.z) + (v2.w - v0.w);
                mg.z = magf(gx, gy); cc.z = (unsigned char)octclass(gx, gy);
            }
            {   // t=3: r=(p0,p1,p2)
                float gx = (p0 - v0.z) + 2.0f * (p1 - v1.z) + (p2 - v2.z);
                float gy = (v2.z - v0.z) + 2.0f * (v2.w - v0.w) + (p2 - p0);
                mg.w = magf(gx, gy); cc.w = (unsigned char)octclass(gx, gy);
            }
            *(float4*)&smg[i][4 * g] = mg;
            *(uchar4*)&scl[i][4 * g] = cc;
        }
    }
    __syncthreads();

    // ---- stage 5: NMS + store, 32 rows x 16 groups of 4 px ----
    const unsigned DY = 0x0001u, DX = 0x0122u;
    const bool border = reflX | reflY;

    #pragma unroll
    for (int k = 0; k < 2; k++) {
        int u = tid + k * NT;
        int iy = u >> 4, g = u & 15;
        int ii = iy + 1;
        int j0 = 4 * g + 2;

        float2 ca = *(const float2*)&smg[ii][j0];
        float2 cb = *(const float2*)&smg[ii][j0 + 2];
        uchar2 ka = *(const uchar2*)&scl[ii][j0];
        uchar2 kb = *(const uchar2*)&scl[ii][j0 + 2];
        float mcv[4] = {ca.x, ca.y, cb.x, cb.y};
        int   cls[4] = {ka.x, ka.y, kb.x, kb.y};

        float4 res;
        float* rp = &res.x;
        #pragma unroll
        for (int t = 0; t < 4; t++) {
            int s  = cls[t] * 4;
            int dy = (int)((DY >> s) & 0xFu) - 1;
            int dx = (int)((DX >> s) & 0xFu) - 1;
            int jj = j0 + t;
            float mp = smg[ii + dy][jj + dx];
            float mq = smg[ii - dy][jj - dx];
            if (border) {
                int ay = by0 + iy, ax = bx0 + 4 * g + t;
                if (!((unsigned)(ay + dy) < 512u && (unsigned)(ax + dx) < 512u)) mp = 0.0f;
                if (!((unsigned)(ay - dy) < 512u && (unsigned)(ax - dx) < 512u)) mq = 0.0f;
            }
            float m = mcv[t];
            rp[t] = (m > mp && m > mq) ? m : 0.0f;
        }
        *(float4*)&out[((size_t)blockIdx.z * 512 + by0 + iy) * 512 + bx0 + 4 * g] = res;
    }
}

extern "C" void kernel_launch(void* const* d_in, const int* in_sizes, int n_in,
                              void* d_out, int out_size)
{
    (void)in_sizes; (void)n_in; (void)out_size;
    const float* data = (const float*)d_in[0];
    float* out = (float*)d_out;

    dim3 grid(8, 16, 16);
    dim3 block(NT);
    canny_fused_kernel<<<grid, block>>>(data, out);
}